// round 2
// baseline (speedup 1.0000x reference)
#include <cuda_runtime.h>
#include <math.h>

// Problem dims (fixed by the dataset)
#define Bq 4
#define Tq 2048
#define Dq 1024
#define Hq 2048
#define Eq 8
#define Kq 2
#define Nq (Bq*Tq)          // 8192 tokens
#define NROWS (Nq*Kq)       // 16384 (token, expert) pairs
#define MTILES 64           // worst case: one expert gets all 8192 tokens -> 64 tiles of 128

// -------------------- scratch (device globals; no allocation allowed) ------
__device__ int   g_count[Eq];
__device__ int   g_offset[Eq];
__device__ int   g_cursor[Eq];
__device__ float g_imp_sum[Eq];
__device__ float g_ent_sum;
__device__ int   g_tk_idx[Nq*Kq];
__device__ float g_tk_gate[Nq*Kq];
__device__ int   g_row_token[NROWS];
__device__ float g_row_gate[NROWS];
__device__ float g_h[(size_t)NROWS*Hq];   // 128 MiB intermediate (gelu output)
__device__ float g_z[(size_t)Nq*Dq];      // residual accumulator (x + moe_out)

// -------------------- init ------------------------------------------------
__global__ void init_k() {
    int i = threadIdx.x;
    if (i < Eq) { g_count[i] = 0; g_imp_sum[i] = 0.f; }
    if (i == Eq) g_ent_sum = 0.f;
}

// -------------------- router: one warp per token --------------------------
__global__ void router_k(const float* __restrict__ x,
                         const float* __restrict__ gw,
                         const float* __restrict__ gb) {
    __shared__ float s_imp[Eq];
    __shared__ int   s_cnt[Eq];
    __shared__ float s_ent;
    int tid = threadIdx.x;
    if (tid < Eq) { s_imp[tid] = 0.f; s_cnt[tid] = 0; }
    if (tid == Eq) s_ent = 0.f;
    __syncthreads();

    int warp = tid >> 5, lane = tid & 31;
    int t = blockIdx.x * 8 + warp;   // 8 warps per block, grid = Nq/8

    float acc[Eq];
    #pragma unroll
    for (int e = 0; e < Eq; e++) acc[e] = 0.f;

    const float* xr = x + (size_t)t * Dq;
    for (int d = lane; d < Dq; d += 32) {
        float xv = xr[d];
        const float* gwr = gw + d * Eq;
        #pragma unroll
        for (int e = 0; e < Eq; e++) acc[e] += xv * gwr[e];
    }
    #pragma unroll
    for (int e = 0; e < Eq; e++) {
        #pragma unroll
        for (int o = 16; o > 0; o >>= 1)
            acc[e] += __shfl_down_sync(0xffffffffu, acc[e], o);
    }

    if (lane == 0) {
        float lg[Eq], p[Eq];
        float mx = -1e30f;
        #pragma unroll
        for (int e = 0; e < Eq; e++) { lg[e] = acc[e] + gb[e]; mx = fmaxf(mx, lg[e]); }
        float se = 0.f;
        #pragma unroll
        for (int e = 0; e < Eq; e++) { p[e] = expf(lg[e] - mx); se += p[e]; }
        float inv = 1.f / se;
        float ent = 0.f;
        #pragma unroll
        for (int e = 0; e < Eq; e++) {
            p[e] *= inv;
            ent -= p[e] * logf(p[e] + 1e-8f);
            atomicAdd(&s_imp[e], p[e]);
        }
        // top-2 (first occurrence wins ties, matching jax.lax.top_k)
        float bv = -1e30f, sv = -1e30f; int bi = 0, si = 0;
        #pragma unroll
        for (int e = 0; e < Eq; e++) {
            float v = lg[e];
            if (v > bv) { sv = bv; si = bi; bv = v; bi = e; }
            else if (v > sv) { sv = v; si = e; }
        }
        float g0 = 1.f / (1.f + expf(sv - bv));
        float g1 = 1.f - g0;
        g_tk_idx[2*t]   = bi;  g_tk_idx[2*t+1]  = si;
        g_tk_gate[2*t]  = g0;  g_tk_gate[2*t+1] = g1;
        atomicAdd(&s_cnt[bi], 1);
        atomicAdd(&s_cnt[si], 1);
        atomicAdd(&s_ent, ent);
    }
    __syncthreads();
    if (tid < Eq) {
        if (s_cnt[tid]) atomicAdd(&g_count[tid], s_cnt[tid]);
        atomicAdd(&g_imp_sum[tid], s_imp[tid]);
    }
    if (tid == Eq) atomicAdd(&g_ent_sum, s_ent);
}

// -------------------- finalize scalars + prefix offsets -------------------
__global__ void finalize_k(float* __restrict__ out_tail) {
    if (threadIdx.x != 0) return;
    int c = 0;
    #pragma unroll
    for (int e = 0; e < Eq; e++) { g_offset[e] = c; g_cursor[e] = c; c += g_count[e]; }
    float invN = 1.f / (float)Nq;
    float bal = 0.f, ue = 0.f;
    #pragma unroll
    for (int e = 0; e < Eq; e++) {
        float imp  = g_imp_sum[e] * invN;
        float load = (float)g_count[e] * invN;
        bal += imp * load;
        ue  -= load * logf(load + 1e-8f);
        out_tail[3 + e]  = load;
        out_tail[11 + e] = imp;
    }
    out_tail[0] = (float)Eq * bal;       // balance_loss
    out_tail[1] = g_ent_sum * invN;      // entropy
    out_tail[2] = ue;                    // utilization_entropy
}

// -------------------- scatter: compact per-expert row lists ---------------
__global__ void scatter_k() {
    int t = blockIdx.x * blockDim.x + threadIdx.x;
    if (t >= Nq) return;
    #pragma unroll
    for (int k = 0; k < Kq; k++) {
        int e = g_tk_idx[2*t + k];
        int pos = atomicAdd(&g_cursor[e], 1);
        g_row_token[pos] = t;
        g_row_gate[pos]  = g_tk_gate[2*t + k];
    }
}

// -------------------- z = x (residual init) -------------------------------
__global__ void zinit_k(const float* __restrict__ x) {
    size_t i = (size_t)blockIdx.x * blockDim.x + threadIdx.x;   // in float4 units
    reinterpret_cast<float4*>(g_z)[i] = reinterpret_cast<const float4*>(x)[i];
}

// -------------------- GEMM1: h = gelu(Xg @ W1[e] + b1[e]) -----------------
// Tile: 128x128x16, 256 threads, 8x8 per thread.
__global__ __launch_bounds__(256) void gemm1_k(const float* __restrict__ x,
                                               const float* __restrict__ W1,
                                               const float* __restrict__ b1) {
    int e  = blockIdx.x >> 6;
    int mt = blockIdx.x & 63;
    int rows = g_count[e];
    int m0 = mt * 128;
    if (m0 >= rows) return;
    int base = g_offset[e];
    int n0 = blockIdx.y * 128;

    __shared__ __align__(16) float As[16][128];
    __shared__ __align__(16) float Bs[16][128];

    int tid = threadIdx.x;
    int ar0 = tid >> 2,          ak0 = (tid & 3) * 4;
    int ar1 = (tid + 256) >> 2,  ak1 = ((tid + 256) & 3) * 4;
    bool v0 = (m0 + ar0) < rows;
    bool v1 = (m0 + ar1) < rows;
    int tok0 = v0 ? g_row_token[base + m0 + ar0] : 0;
    int tok1 = v1 ? g_row_token[base + m0 + ar1] : 0;
    int br = tid >> 5, bc = (tid & 31) * 4;

    const float* w1e = W1 + (size_t)e * Dq * Hq;
    int tr = (tid >> 4) * 8, tc = (tid & 15) * 8;

    float accv[8][8];
    #pragma unroll
    for (int i = 0; i < 8; i++)
        #pragma unroll
        for (int j = 0; j < 8; j++) accv[i][j] = 0.f;

    for (int k0 = 0; k0 < Dq; k0 += 16) {
        float4 a0 = v0 ? *(const float4*)(x + (size_t)tok0 * Dq + k0 + ak0)
                       : make_float4(0.f,0.f,0.f,0.f);
        float4 a1 = v1 ? *(const float4*)(x + (size_t)tok1 * Dq + k0 + ak1)
                       : make_float4(0.f,0.f,0.f,0.f);
        float4 bb0 = *(const float4*)(w1e + (size_t)(k0 + br)     * Hq + n0 + bc);
        float4 bb1 = *(const float4*)(w1e + (size_t)(k0 + br + 8) * Hq + n0 + bc);
        __syncthreads();
        As[ak0+0][ar0] = a0.x; As[ak0+1][ar0] = a0.y; As[ak0+2][ar0] = a0.z; As[ak0+3][ar0] = a0.w;
        As[ak1+0][ar1] = a1.x; As[ak1+1][ar1] = a1.y; As[ak1+2][ar1] = a1.z; As[ak1+3][ar1] = a1.w;
        *(float4*)&Bs[br][bc]     = bb0;
        *(float4*)&Bs[br + 8][bc] = bb1;
        __syncthreads();
        #pragma unroll
        for (int kk = 0; kk < 16; kk++) {
            float ra[8], rb[8];
            *(float4*)ra       = *(float4*)&As[kk][tr];
            *(float4*)(ra + 4) = *(float4*)&As[kk][tr + 4];
            *(float4*)rb       = *(float4*)&Bs[kk][tc];
            *(float4*)(rb + 4) = *(float4*)&Bs[kk][tc + 4];
            #pragma unroll
            for (int i = 0; i < 8; i++)
                #pragma unroll
                for (int j = 0; j < 8; j++) accv[i][j] += ra[i] * rb[j];
        }
    }

    #pragma unroll
    for (int i = 0; i < 8; i++) {
        int m = m0 + tr + i;
        if (m < rows) {
            int gr = base + m;
            float* hout = g_h + (size_t)gr * Hq + n0 + tc;
            #pragma unroll
            for (int j = 0; j < 8; j++) {
                float c = accv[i][j] + b1[e * Hq + n0 + tc + j];
                hout[j] = 0.5f * c * (1.f + erff(c * 0.70710678118654752f));
            }
        }
    }
}

// -------------------- GEMM2: z += gate * (H @ W2[e] + b2[e]) --------------
__global__ __launch_bounds__(256) void gemm2_k(const float* __restrict__ W2,
                                               const float* __restrict__ b2) {
    int e  = blockIdx.x >> 6;
    int mt = blockIdx.x & 63;
    int rows = g_count[e];
    int m0 = mt * 128;
    if (m0 >= rows) return;
    int base = g_offset[e];
    int n0 = blockIdx.y * 128;

    __shared__ __align__(16) float As[16][128];
    __shared__ __align__(16) float Bs[16][128];

    int tid = threadIdx.x;
    int ar0 = tid >> 2,          ak0 = (tid & 3) * 4;
    int ar1 = (tid + 256) >> 2,  ak1 = ((tid + 256) & 3) * 4;
    bool v0 = (m0 + ar0) < rows;
    bool v1 = (m0 + ar1) < rows;
    size_t arow0 = (size_t)(base + m0 + (v0 ? ar0 : 0)) * Hq;
    size_t arow1 = (size_t)(base + m0 + (v1 ? ar1 : 0)) * Hq;
    int br = tid >> 5, bc = (tid & 31) * 4;

    const float* w2e = W2 + (size_t)e * Hq * Dq;
    int tr = (tid >> 4) * 8, tc = (tid & 15) * 8;

    float accv[8][8];
    #pragma unroll
    for (int i = 0; i < 8; i++)
        #pragma unroll
        for (int j = 0; j < 8; j++) accv[i][j] = 0.f;

    for (int k0 = 0; k0 < Hq; k0 += 16) {
        float4 a0 = v0 ? *(const float4*)(g_h + arow0 + k0 + ak0) : make_float4(0.f,0.f,0.f,0.f);
        float4 a1 = v1 ? *(const float4*)(g_h + arow1 + k0 + ak1) : make_float4(0.f,0.f,0.f,0.f);
        float4 bb0 = *(const float4*)(w2e + (size_t)(k0 + br)     * Dq + n0 + bc);
        float4 bb1 = *(const float4*)(w2e + (size_t)(k0 + br + 8) * Dq + n0 + bc);
        __syncthreads();
        As[ak0+0][ar0] = a0.x; As[ak0+1][ar0] = a0.y; As[ak0+2][ar0] = a0.z; As[ak0+3][ar0] = a0.w;
        As[ak1+0][ar1] = a1.x; As[ak1+1][ar1] = a1.y; As[ak1+2][ar1] = a1.z; As[ak1+3][ar1] = a1.w;
        *(float4*)&Bs[br][bc]     = bb0;
        *(float4*)&Bs[br + 8][bc] = bb1;
        __syncthreads();
        #pragma unroll
        for (int kk = 0; kk < 16; kk++) {
            float ra[8], rb[8];
            *(float4*)ra       = *(float4*)&As[kk][tr];
            *(float4*)(ra + 4) = *(float4*)&As[kk][tr + 4];
            *(float4*)rb       = *(float4*)&Bs[kk][tc];
            *(float4*)(rb + 4) = *(float4*)&Bs[kk][tc + 4];
            #pragma unroll
            for (int i = 0; i < 8; i++)
                #pragma unroll
                for (int j = 0; j < 8; j++) accv[i][j] += ra[i] * rb[j];
        }
    }

    #pragma unroll
    for (int i = 0; i < 8; i++) {
        int m = m0 + tr + i;
        if (m < rows) {
            int gr = base + m;
            int tok = g_row_token[gr];
            float gt = g_row_gate[gr];
            float* zr = g_z + (size_t)tok * Dq + n0 + tc;
            #pragma unroll
            for (int j = 0; j < 8; j++) {
                float v = gt * (accv[i][j] + b2[e * Dq + n0 + tc + j]);
                atomicAdd(&zr[j], v);
            }
        }
    }
}

// -------------------- layernorm: one block (256 thr) per token ------------
__global__ void ln_k(const float* __restrict__ gamma,
                     const float* __restrict__ beta,
                     float* __restrict__ out) {
    int t = blockIdx.x;
    int tid = threadIdx.x;
    const float4* zr = reinterpret_cast<const float4*>(g_z + (size_t)t * Dq);
    float4 v = zr[tid];           // 256 * 4 = 1024 elements exactly
    float s  = v.x + v.y + v.z + v.w;
    float ss = v.x*v.x + v.y*v.y + v.z*v.z + v.w*v.w;

    #pragma unroll
    for (int o = 16; o > 0; o >>= 1) {
        s  += __shfl_down_sync(0xffffffffu, s, o);
        ss += __shfl_down_sync(0xffffffffu, ss, o);
    }
    __shared__ float rs[8], rss[8];
    int warp = tid >> 5, lane = tid & 31;
    if (lane == 0) { rs[warp] = s; rss[warp] = ss; }
    __syncthreads();
    if (warp == 0) {
        float a = (lane < 8) ? rs[lane] : 0.f;
        float b = (lane < 8) ? rss[lane] : 0.f;
        #pragma unroll
        for (int o = 4; o > 0; o >>= 1) {
            a += __shfl_down_sync(0xffffffffu, a, o);
            b += __shfl_down_sync(0xffffffffu, b, o);
        }
        if (lane == 0) { rs[0] = a; rss[0] = b; }
    }
    __syncthreads();
    float mu  = rs[0] * (1.f / Dq);
    float var = rss[0] * (1.f / Dq) - mu * mu;
    float rstd = rsqrtf(var + 1e-5f);

    int i = tid * 4;
    float4 g = reinterpret_cast<const float4*>(gamma)[tid];
    float4 bta = reinterpret_cast<const float4*>(beta)[tid];
    float4 o4;
    o4.x = (v.x - mu) * rstd * g.x + bta.x;
    o4.y = (v.y - mu) * rstd * g.y + bta.y;
    o4.z = (v.z - mu) * rstd * g.z + bta.z;
    o4.w = (v.w - mu) * rstd * g.w + bta.w;
    reinterpret_cast<float4*>(out + (size_t)t * Dq)[tid] = o4;
    (void)i;
}

// -------------------- launch ----------------------------------------------
extern "C" void kernel_launch(void* const* d_in, const int* in_sizes, int n_in,
                              void* d_out, int out_size) {
    const float* x     = (const float*)d_in[0];
    const float* gw    = (const float*)d_in[1];
    const float* gb    = (const float*)d_in[2];
    const float* W1    = (const float*)d_in[3];
    const float* b1    = (const float*)d_in[4];
    const float* W2    = (const float*)d_in[5];
    const float* b2    = (const float*)d_in[6];
    const float* gamma = (const float*)d_in[7];
    const float* beta  = (const float*)d_in[8];
    float* out = (float*)d_out;

    init_k<<<1, 32>>>();
    router_k<<<Nq / 8, 256>>>(x, gw, gb);
    finalize_k<<<1, 32>>>(out + (size_t)Nq * Dq);
    scatter_k<<<Nq / 256, 256>>>();
    zinit_k<<<(Nq * Dq / 4) / 256, 256>>>(x);
    gemm1_k<<<dim3(Eq * MTILES, Hq / 128), 256>>>(x, W1, b1);
    gemm2_k<<<dim3(Eq * MTILES, Dq / 128), 256>>>(W2, b2);
    ln_k<<<Nq, 256>>>(gamma, beta, out);
    (void)in_sizes; (void)n_in; (void)out_size;
}

// round 3
// speedup vs baseline: 2.3909x; 2.3909x over previous
#include <cuda_runtime.h>
#include <math.h>
#include <stdint.h>

// Problem dims (fixed by the dataset)
#define Bq 4
#define Tq 2048
#define Dq 1024
#define Hq 2048
#define Eq 8
#define Kq 2
#define Nq (Bq*Tq)          // 8192 tokens
#define NROWS (Nq*Kq)       // 16384 (token, expert) pairs
#define MTILES 64           // worst case: one expert gets all 8192 tokens -> 64 tiles of 128

// -------------------- scratch (device globals; no allocation allowed) ------
__device__ int   g_count[Eq];
__device__ int   g_offset[Eq];
__device__ int   g_cursor[Eq];
__device__ float g_imp_sum[Eq];
__device__ float g_ent_sum;
__device__ int   g_tk_idx[Nq*Kq];
__device__ float g_tk_gate[Nq*Kq];
__device__ int   g_row_token[NROWS];
__device__ float g_row_gate[NROWS];
__device__ float g_h[(size_t)NROWS*Hq];   // 128 MiB intermediate (gelu output)
__device__ float g_z[(size_t)Nq*Dq];      // residual accumulator (x + moe_out)

// -------------------- tf32 helpers ----------------------------------------
__device__ __forceinline__ uint32_t f2tf32(float f) {
    uint32_t u;
    asm("cvt.rna.tf32.f32 %0, %1;" : "=r"(u) : "f"(f));
    return u;
}

__device__ __forceinline__ void mma8(float* d,
                                     uint32_t a0, uint32_t a1, uint32_t a2, uint32_t a3,
                                     uint32_t b0, uint32_t b1) {
    asm volatile("mma.sync.aligned.m16n8k8.row.col.f32.tf32.tf32.f32 "
                 "{%0,%1,%2,%3}, {%4,%5,%6,%7}, {%8,%9}, {%0,%1,%2,%3};"
                 : "+f"(d[0]), "+f"(d[1]), "+f"(d[2]), "+f"(d[3])
                 : "r"(a0), "r"(a1), "r"(a2), "r"(a3), "r"(b0), "r"(b1));
}

__device__ __forceinline__ float gelu_exact(float c) {
    return 0.5f * c * (1.f + erff(c * 0.70710678118654752f));
}

// -------------------- init ------------------------------------------------
__global__ void init_k() {
    int i = threadIdx.x;
    if (i < Eq) { g_count[i] = 0; g_imp_sum[i] = 0.f; }
    if (i == Eq) g_ent_sum = 0.f;
}

// -------------------- router: one warp per token --------------------------
__global__ void router_k(const float* __restrict__ x,
                         const float* __restrict__ gw,
                         const float* __restrict__ gb) {
    __shared__ float s_imp[Eq];
    __shared__ int   s_cnt[Eq];
    __shared__ float s_ent;
    int tid = threadIdx.x;
    if (tid < Eq) { s_imp[tid] = 0.f; s_cnt[tid] = 0; }
    if (tid == Eq) s_ent = 0.f;
    __syncthreads();

    int warp = tid >> 5, lane = tid & 31;
    int t = blockIdx.x * 8 + warp;   // 8 warps per block, grid = Nq/8

    float acc[Eq];
    #pragma unroll
    for (int e = 0; e < Eq; e++) acc[e] = 0.f;

    const float* xr = x + (size_t)t * Dq;
    for (int d = lane; d < Dq; d += 32) {
        float xv = xr[d];
        const float* gwr = gw + d * Eq;
        #pragma unroll
        for (int e = 0; e < Eq; e++) acc[e] += xv * gwr[e];
    }
    #pragma unroll
    for (int e = 0; e < Eq; e++) {
        #pragma unroll
        for (int o = 16; o > 0; o >>= 1)
            acc[e] += __shfl_down_sync(0xffffffffu, acc[e], o);
    }

    if (lane == 0) {
        float lg[Eq], p[Eq];
        float mx = -1e30f;
        #pragma unroll
        for (int e = 0; e < Eq; e++) { lg[e] = acc[e] + gb[e]; mx = fmaxf(mx, lg[e]); }
        float se = 0.f;
        #pragma unroll
        for (int e = 0; e < Eq; e++) { p[e] = expf(lg[e] - mx); se += p[e]; }
        float inv = 1.f / se;
        float ent = 0.f;
        #pragma unroll
        for (int e = 0; e < Eq; e++) {
            p[e] *= inv;
            ent -= p[e] * logf(p[e] + 1e-8f);
            atomicAdd(&s_imp[e], p[e]);
        }
        // top-2 (first occurrence wins ties, matching jax.lax.top_k)
        float bv = -1e30f, sv = -1e30f; int bi = 0, si = 0;
        #pragma unroll
        for (int e = 0; e < Eq; e++) {
            float v = lg[e];
            if (v > bv) { sv = bv; si = bi; bv = v; bi = e; }
            else if (v > sv) { sv = v; si = e; }
        }
        float g0 = 1.f / (1.f + expf(sv - bv));
        float g1 = 1.f - g0;
        g_tk_idx[2*t]   = bi;  g_tk_idx[2*t+1]  = si;
        g_tk_gate[2*t]  = g0;  g_tk_gate[2*t+1] = g1;
        atomicAdd(&s_cnt[bi], 1);
        atomicAdd(&s_cnt[si], 1);
        atomicAdd(&s_ent, ent);
    }
    __syncthreads();
    if (tid < Eq) {
        if (s_cnt[tid]) atomicAdd(&g_count[tid], s_cnt[tid]);
        atomicAdd(&g_imp_sum[tid], s_imp[tid]);
    }
    if (tid == Eq) atomicAdd(&g_ent_sum, s_ent);
}

// -------------------- finalize scalars + prefix offsets -------------------
__global__ void finalize_k(float* __restrict__ out_tail) {
    if (threadIdx.x != 0) return;
    int c = 0;
    #pragma unroll
    for (int e = 0; e < Eq; e++) { g_offset[e] = c; g_cursor[e] = c; c += g_count[e]; }
    float invN = 1.f / (float)Nq;
    float bal = 0.f, ue = 0.f;
    #pragma unroll
    for (int e = 0; e < Eq; e++) {
        float imp  = g_imp_sum[e] * invN;
        float load = (float)g_count[e] * invN;
        bal += imp * load;
        ue  -= load * logf(load + 1e-8f);
        out_tail[3 + e]  = load;
        out_tail[11 + e] = imp;
    }
    out_tail[0] = (float)Eq * bal;       // balance_loss
    out_tail[1] = g_ent_sum * invN;      // entropy
    out_tail[2] = ue;                    // utilization_entropy
}

// -------------------- scatter: compact per-expert row lists ---------------
__global__ void scatter_k() {
    int t = blockIdx.x * blockDim.x + threadIdx.x;
    if (t >= Nq) return;
    #pragma unroll
    for (int k = 0; k < Kq; k++) {
        int e = g_tk_idx[2*t + k];
        int pos = atomicAdd(&g_cursor[e], 1);
        g_row_token[pos] = t;
        g_row_gate[pos]  = g_tk_gate[2*t + k];
    }
}

// -------------------- z = x (residual init) -------------------------------
__global__ void zinit_k(const float* __restrict__ x) {
    size_t i = (size_t)blockIdx.x * blockDim.x + threadIdx.x;   // in float4 units
    reinterpret_cast<float4*>(g_z)[i] = reinterpret_cast<const float4*>(x)[i];
}

// ==========================================================================
// tf32 tensor-core grouped GEMMs
// Tile 128x128x16, 256 threads = 8 warps in 2(m) x 4(n); warp tile 64x32.
// Fragments: mma.m16n8k8 tf32, 4x4 frag grid per warp, fp32 accumulate.
// Smem stride 136 (== 8 mod 32) -> conflict-free fragment loads.
// ==========================================================================

// -------------------- GEMM1: h = gelu(Xg @ W1[e] + b1[e]) -----------------
__global__ __launch_bounds__(256) void gemm1_k(const float* __restrict__ x,
                                               const float* __restrict__ W1,
                                               const float* __restrict__ b1) {
    int e  = blockIdx.x >> 6;
    int mt = blockIdx.x & 63;
    int rows = g_count[e];
    int m0 = mt * 128;
    if (m0 >= rows) return;
    int base = g_offset[e];
    int n0 = blockIdx.y * 128;

    __shared__ uint32_t As[16][136];
    __shared__ uint32_t Bs[16][136];

    int tid = threadIdx.x;
    int ar = tid >> 2, ak = (tid & 3) * 4;          // A: rows ar, ar+64; k quad
    bool v0 = (m0 + ar)      < rows;
    bool v1 = (m0 + ar + 64) < rows;
    int tok0 = v0 ? g_row_token[base + m0 + ar]      : 0;
    int tok1 = v1 ? g_row_token[base + m0 + ar + 64] : 0;
    int br = tid >> 5, bc = (tid & 31) * 4;         // B: rows br, br+8

    const float* w1e = W1 + (size_t)e * Dq * Hq;

    int warp = tid >> 5, lane = tid & 31;
    int wm = (warp >> 2) * 64, wn = (warp & 3) * 32;
    int qr = lane >> 2, qc = lane & 3;

    float acc[4][4][4];
    #pragma unroll
    for (int mi = 0; mi < 4; mi++)
        #pragma unroll
        for (int ni = 0; ni < 4; ni++)
            #pragma unroll
            for (int j = 0; j < 4; j++) acc[mi][ni][j] = 0.f;

    for (int k0 = 0; k0 < Dq; k0 += 16) {
        float4 a0 = v0 ? *(const float4*)(x + (size_t)tok0 * Dq + k0 + ak)
                       : make_float4(0.f,0.f,0.f,0.f);
        float4 a1 = v1 ? *(const float4*)(x + (size_t)tok1 * Dq + k0 + ak)
                       : make_float4(0.f,0.f,0.f,0.f);
        float4 f0 = *(const float4*)(w1e + (size_t)(k0 + br)     * Hq + n0 + bc);
        float4 f1 = *(const float4*)(w1e + (size_t)(k0 + br + 8) * Hq + n0 + bc);
        __syncthreads();
        As[ak+0][ar]    = f2tf32(a0.x); As[ak+1][ar]    = f2tf32(a0.y);
        As[ak+2][ar]    = f2tf32(a0.z); As[ak+3][ar]    = f2tf32(a0.w);
        As[ak+0][ar+64] = f2tf32(a1.x); As[ak+1][ar+64] = f2tf32(a1.y);
        As[ak+2][ar+64] = f2tf32(a1.z); As[ak+3][ar+64] = f2tf32(a1.w);
        {
            uint4 u0 = make_uint4(f2tf32(f0.x), f2tf32(f0.y), f2tf32(f0.z), f2tf32(f0.w));
            uint4 u1 = make_uint4(f2tf32(f1.x), f2tf32(f1.y), f2tf32(f1.z), f2tf32(f1.w));
            *(uint4*)&Bs[br][bc]     = u0;
            *(uint4*)&Bs[br + 8][bc] = u1;
        }
        __syncthreads();
        #pragma unroll
        for (int ks = 0; ks < 16; ks += 8) {
            uint32_t af[4][4], bf[4][2];
            #pragma unroll
            for (int mi = 0; mi < 4; mi++) {
                int mb = wm + mi * 16 + qr;
                af[mi][0] = As[ks + qc][mb];
                af[mi][1] = As[ks + qc][mb + 8];
                af[mi][2] = As[ks + qc + 4][mb];
                af[mi][3] = As[ks + qc + 4][mb + 8];
            }
            #pragma unroll
            for (int ni = 0; ni < 4; ni++) {
                int nb = wn + ni * 8 + qr;
                bf[ni][0] = Bs[ks + qc][nb];
                bf[ni][1] = Bs[ks + qc + 4][nb];
            }
            #pragma unroll
            for (int mi = 0; mi < 4; mi++)
                #pragma unroll
                for (int ni = 0; ni < 4; ni++)
                    mma8(acc[mi][ni], af[mi][0], af[mi][1], af[mi][2], af[mi][3],
                         bf[ni][0], bf[ni][1]);
        }
    }

    // epilogue: bias + exact gelu -> g_h
    #pragma unroll
    for (int mi = 0; mi < 4; mi++) {
        #pragma unroll
        for (int h = 0; h < 2; h++) {
            int r = wm + mi * 16 + qr + h * 8;
            if (m0 + r < rows) {
                size_t gr = (size_t)(base + m0 + r);
                float* hrow = g_h + gr * Hq;
                #pragma unroll
                for (int ni = 0; ni < 4; ni++) {
                    int c = n0 + wn + ni * 8 + qc * 2;
                    float u = acc[mi][ni][h*2+0] + b1[e * Hq + c];
                    float v = acc[mi][ni][h*2+1] + b1[e * Hq + c + 1];
                    hrow[c]     = gelu_exact(u);
                    hrow[c + 1] = gelu_exact(v);
                }
            }
        }
    }
}

// -------------------- GEMM2: z += gate * (H @ W2[e] + b2[e]) --------------
__global__ __launch_bounds__(256) void gemm2_k(const float* __restrict__ W2,
                                               const float* __restrict__ b2) {
    int e  = blockIdx.x >> 6;
    int mt = blockIdx.x & 63;
    int rows = g_count[e];
    int m0 = mt * 128;
    if (m0 >= rows) return;
    int base = g_offset[e];
    int n0 = blockIdx.y * 128;

    __shared__ uint32_t As[16][136];
    __shared__ uint32_t Bs[16][136];

    int tid = threadIdx.x;
    int ar = tid >> 2, ak = (tid & 3) * 4;
    bool v0 = (m0 + ar)      < rows;
    bool v1 = (m0 + ar + 64) < rows;
    size_t arow0 = (size_t)(base + m0 + (v0 ? ar      : 0)) * Hq;
    size_t arow1 = (size_t)(base + m0 + (v1 ? ar + 64 : 0)) * Hq;
    int br = tid >> 5, bc = (tid & 31) * 4;

    const float* w2e = W2 + (size_t)e * Hq * Dq;

    int warp = tid >> 5, lane = tid & 31;
    int wm = (warp >> 2) * 64, wn = (warp & 3) * 32;
    int qr = lane >> 2, qc = lane & 3;

    float acc[4][4][4];
    #pragma unroll
    for (int mi = 0; mi < 4; mi++)
        #pragma unroll
        for (int ni = 0; ni < 4; ni++)
            #pragma unroll
            for (int j = 0; j < 4; j++) acc[mi][ni][j] = 0.f;

    for (int k0 = 0; k0 < Hq; k0 += 16) {
        float4 a0 = v0 ? *(const float4*)(g_h + arow0 + k0 + ak) : make_float4(0.f,0.f,0.f,0.f);
        float4 a1 = v1 ? *(const float4*)(g_h + arow1 + k0 + ak) : make_float4(0.f,0.f,0.f,0.f);
        float4 f0 = *(const float4*)(w2e + (size_t)(k0 + br)     * Dq + n0 + bc);
        float4 f1 = *(const float4*)(w2e + (size_t)(k0 + br + 8) * Dq + n0 + bc);
        __syncthreads();
        As[ak+0][ar]    = f2tf32(a0.x); As[ak+1][ar]    = f2tf32(a0.y);
        As[ak+2][ar]    = f2tf32(a0.z); As[ak+3][ar]    = f2tf32(a0.w);
        As[ak+0][ar+64] = f2tf32(a1.x); As[ak+1][ar+64] = f2tf32(a1.y);
        As[ak+2][ar+64] = f2tf32(a1.z); As[ak+3][ar+64] = f2tf32(a1.w);
        {
            uint4 u0 = make_uint4(f2tf32(f0.x), f2tf32(f0.y), f2tf32(f0.z), f2tf32(f0.w));
            uint4 u1 = make_uint4(f2tf32(f1.x), f2tf32(f1.y), f2tf32(f1.z), f2tf32(f1.w));
            *(uint4*)&Bs[br][bc]     = u0;
            *(uint4*)&Bs[br + 8][bc] = u1;
        }
        __syncthreads();
        #pragma unroll
        for (int ks = 0; ks < 16; ks += 8) {
            uint32_t af[4][4], bf[4][2];
            #pragma unroll
            for (int mi = 0; mi < 4; mi++) {
                int mb = wm + mi * 16 + qr;
                af[mi][0] = As[ks + qc][mb];
                af[mi][1] = As[ks + qc][mb + 8];
                af[mi][2] = As[ks + qc + 4][mb];
                af[mi][3] = As[ks + qc + 4][mb + 8];
            }
            #pragma unroll
            for (int ni = 0; ni < 4; ni++) {
                int nb = wn + ni * 8 + qr;
                bf[ni][0] = Bs[ks + qc][nb];
                bf[ni][1] = Bs[ks + qc + 4][nb];
            }
            #pragma unroll
            for (int mi = 0; mi < 4; mi++)
                #pragma unroll
                for (int ni = 0; ni < 4; ni++)
                    mma8(acc[mi][ni], af[mi][0], af[mi][1], af[mi][2], af[mi][3],
                         bf[ni][0], bf[ni][1]);
        }
    }

    // epilogue: gate * (acc + b2) scattered into residual accumulator
    #pragma unroll
    for (int mi = 0; mi < 4; mi++) {
        #pragma unroll
        for (int h = 0; h < 2; h++) {
            int r = wm + mi * 16 + qr + h * 8;
            if (m0 + r < rows) {
                int gr = base + m0 + r;
                int tok  = g_row_token[gr];
                float gt = g_row_gate[gr];
                float* zr = g_z + (size_t)tok * Dq;
                #pragma unroll
                for (int ni = 0; ni < 4; ni++) {
                    int c = n0 + wn + ni * 8 + qc * 2;
                    atomicAdd(&zr[c],     gt * (acc[mi][ni][h*2+0] + b2[e * Dq + c]));
                    atomicAdd(&zr[c + 1], gt * (acc[mi][ni][h*2+1] + b2[e * Dq + c + 1]));
                }
            }
        }
    }
}

// -------------------- layernorm: one block (256 thr) per token ------------
__global__ void ln_k(const float* __restrict__ gamma,
                     const float* __restrict__ beta,
                     float* __restrict__ out) {
    int t = blockIdx.x;
    int tid = threadIdx.x;
    const float4* zr = reinterpret_cast<const float4*>(g_z + (size_t)t * Dq);
    float4 v = zr[tid];           // 256 * 4 = 1024 elements exactly
    float s  = v.x + v.y + v.z + v.w;
    float ss = v.x*v.x + v.y*v.y + v.z*v.z + v.w*v.w;

    #pragma unroll
    for (int o = 16; o > 0; o >>= 1) {
        s  += __shfl_down_sync(0xffffffffu, s, o);
        ss += __shfl_down_sync(0xffffffffu, ss, o);
    }
    __shared__ float rs[8], rss[8];
    int warp = tid >> 5, lane = tid & 31;
    if (lane == 0) { rs[warp] = s; rss[warp] = ss; }
    __syncthreads();
    if (warp == 0) {
        float a = (lane < 8) ? rs[lane] : 0.f;
        float b = (lane < 8) ? rss[lane] : 0.f;
        #pragma unroll
        for (int o = 4; o > 0; o >>= 1) {
            a += __shfl_down_sync(0xffffffffu, a, o);
            b += __shfl_down_sync(0xffffffffu, b, o);
        }
        if (lane == 0) { rs[0] = a; rss[0] = b; }
    }
    __syncthreads();
    float mu  = rs[0] * (1.f / Dq);
    float var = rss[0] * (1.f / Dq) - mu * mu;
    float rstd = rsqrtf(var + 1e-5f);

    float4 g = reinterpret_cast<const float4*>(gamma)[tid];
    float4 bta = reinterpret_cast<const float4*>(beta)[tid];
    float4 o4;
    o4.x = (v.x - mu) * rstd * g.x + bta.x;
    o4.y = (v.y - mu) * rstd * g.y + bta.y;
    o4.z = (v.z - mu) * rstd * g.z + bta.z;
    o4.w = (v.w - mu) * rstd * g.w + bta.w;
    reinterpret_cast<float4*>(out + (size_t)t * Dq)[tid] = o4;
}

// -------------------- launch ----------------------------------------------
extern "C" void kernel_launch(void* const* d_in, const int* in_sizes, int n_in,
                              void* d_out, int out_size) {
    const float* x     = (const float*)d_in[0];
    const float* gw    = (const float*)d_in[1];
    const float* gb    = (const float*)d_in[2];
    const float* W1    = (const float*)d_in[3];
    const float* b1    = (const float*)d_in[4];
    const float* W2    = (const float*)d_in[5];
    const float* b2    = (const float*)d_in[6];
    const float* gamma = (const float*)d_in[7];
    const float* beta  = (const float*)d_in[8];
    float* out = (float*)d_out;

    init_k<<<1, 32>>>();
    router_k<<<Nq / 8, 256>>>(x, gw, gb);
    finalize_k<<<1, 32>>>(out + (size_t)Nq * Dq);
    scatter_k<<<Nq / 256, 256>>>();
    zinit_k<<<(Nq * Dq / 4) / 256, 256>>>(x);
    gemm1_k<<<dim3(Eq * MTILES, Hq / 128), 256>>>(x, W1, b1);
    gemm2_k<<<dim3(Eq * MTILES, Dq / 128), 256>>>(W2, b2);
    ln_k<<<Nq, 256>>>(gamma, beta, out);
    (void)in_sizes; (void)n_in; (void)out_size;
}

// round 4
// speedup vs baseline: 2.4197x; 1.0121x over previous
#include <cuda_runtime.h>
#include <math.h>
#include <stdint.h>

// Problem dims (fixed by the dataset)
#define Bq 4
#define Tq 2048
#define Dq 1024
#define Hq 2048
#define Eq 8
#define Kq 2
#define Nq (Bq*Tq)          // 8192 tokens
#define NROWS (Nq*Kq)       // 16384 (token, expert) pairs
#define MTILES 64           // worst case: one expert gets all 8192 tokens

// GEMM tiling
#define KT 32               // k-tile
#define AS_STRIDE 36        // floats per A smem row (128 rows)
#define BS_STRIDE 136       // floats per B smem row (32 rows)
#define A_STAGE_F (128*AS_STRIDE)          // 4608 floats
#define B_STAGE_F (KT*BS_STRIDE)           // 4352 floats
#define STAGE_F   (A_STAGE_F + B_STAGE_F)  // 8960 floats = 35840 B
#define SMEM_BYTES (2*STAGE_F*4)           // 71680 B

// -------------------- scratch (device globals; no allocation allowed) ------
__device__ int   g_count[Eq];
__device__ int   g_offset[Eq];
__device__ int   g_cursor[Eq];
__device__ float g_imp_sum[Eq];
__device__ float g_ent_sum;
__device__ int   g_tk_idx[Nq*Kq];
__device__ float g_tk_gate[Nq*Kq];
__device__ int   g_row_token[NROWS];
__device__ float g_row_gate[NROWS];
__device__ float g_h[(size_t)NROWS*Hq];   // 128 MiB intermediate (gelu output)
__device__ float g_z[(size_t)Nq*Dq];      // residual accumulator (x + moe_out)

// -------------------- helpers ---------------------------------------------
__device__ __forceinline__ void mma8(float* d,
                                     uint32_t a0, uint32_t a1, uint32_t a2, uint32_t a3,
                                     uint32_t b0, uint32_t b1) {
    asm volatile("mma.sync.aligned.m16n8k8.row.col.f32.tf32.tf32.f32 "
                 "{%0,%1,%2,%3}, {%4,%5,%6,%7}, {%8,%9}, {%0,%1,%2,%3};"
                 : "+f"(d[0]), "+f"(d[1]), "+f"(d[2]), "+f"(d[3])
                 : "r"(a0), "r"(a1), "r"(a2), "r"(a3), "r"(b0), "r"(b1));
}

__device__ __forceinline__ void cp16(uint32_t dst, const void* src, int szr) {
    asm volatile("cp.async.cg.shared.global [%0], [%1], 16, %2;"
                 :: "r"(dst), "l"(src), "r"(szr));
}
#define CP_COMMIT() asm volatile("cp.async.commit_group;")
#define CP_WAIT0()  asm volatile("cp.async.wait_group 0;")

__device__ __forceinline__ float gelu_exact(float c) {
    return 0.5f * c * (1.f + erff(c * 0.70710678118654752f));
}

// -------------------- init ------------------------------------------------
__global__ void init_k() {
    int i = threadIdx.x;
    if (i < Eq) { g_count[i] = 0; g_imp_sum[i] = 0.f; }
    if (i == Eq) g_ent_sum = 0.f;
}

// -------------------- router: one warp per token --------------------------
__global__ void router_k(const float* __restrict__ x,
                         const float* __restrict__ gw,
                         const float* __restrict__ gb) {
    __shared__ float s_imp[Eq];
    __shared__ int   s_cnt[Eq];
    __shared__ float s_ent;
    int tid = threadIdx.x;
    if (tid < Eq) { s_imp[tid] = 0.f; s_cnt[tid] = 0; }
    if (tid == Eq) s_ent = 0.f;
    __syncthreads();

    int warp = tid >> 5, lane = tid & 31;
    int t = blockIdx.x * 8 + warp;

    float acc[Eq];
    #pragma unroll
    for (int e = 0; e < Eq; e++) acc[e] = 0.f;

    const float* xr = x + (size_t)t * Dq;
    for (int d = lane; d < Dq; d += 32) {
        float xv = xr[d];
        const float* gwr = gw + d * Eq;
        #pragma unroll
        for (int e = 0; e < Eq; e++) acc[e] += xv * gwr[e];
    }
    #pragma unroll
    for (int e = 0; e < Eq; e++) {
        #pragma unroll
        for (int o = 16; o > 0; o >>= 1)
            acc[e] += __shfl_down_sync(0xffffffffu, acc[e], o);
    }

    if (lane == 0) {
        float lg[Eq], p[Eq];
        float mx = -1e30f;
        #pragma unroll
        for (int e = 0; e < Eq; e++) { lg[e] = acc[e] + gb[e]; mx = fmaxf(mx, lg[e]); }
        float se = 0.f;
        #pragma unroll
        for (int e = 0; e < Eq; e++) { p[e] = expf(lg[e] - mx); se += p[e]; }
        float inv = 1.f / se;
        float ent = 0.f;
        #pragma unroll
        for (int e = 0; e < Eq; e++) {
            p[e] *= inv;
            ent -= p[e] * logf(p[e] + 1e-8f);
            atomicAdd(&s_imp[e], p[e]);
        }
        float bv = -1e30f, sv = -1e30f; int bi = 0, si = 0;
        #pragma unroll
        for (int e = 0; e < Eq; e++) {
            float v = lg[e];
            if (v > bv) { sv = bv; si = bi; bv = v; bi = e; }
            else if (v > sv) { sv = v; si = e; }
        }
        float g0 = 1.f / (1.f + expf(sv - bv));
        float g1 = 1.f - g0;
        g_tk_idx[2*t]   = bi;  g_tk_idx[2*t+1]  = si;
        g_tk_gate[2*t]  = g0;  g_tk_gate[2*t+1] = g1;
        atomicAdd(&s_cnt[bi], 1);
        atomicAdd(&s_cnt[si], 1);
        atomicAdd(&s_ent, ent);
    }
    __syncthreads();
    if (tid < Eq) {
        if (s_cnt[tid]) atomicAdd(&g_count[tid], s_cnt[tid]);
        atomicAdd(&g_imp_sum[tid], s_imp[tid]);
    }
    if (tid == Eq) atomicAdd(&g_ent_sum, s_ent);
}

// -------------------- finalize scalars + prefix offsets -------------------
__global__ void finalize_k(float* __restrict__ out_tail) {
    if (threadIdx.x != 0) return;
    int c = 0;
    #pragma unroll
    for (int e = 0; e < Eq; e++) { g_offset[e] = c; g_cursor[e] = c; c += g_count[e]; }
    float invN = 1.f / (float)Nq;
    float bal = 0.f, ue = 0.f;
    #pragma unroll
    for (int e = 0; e < Eq; e++) {
        float imp  = g_imp_sum[e] * invN;
        float load = (float)g_count[e] * invN;
        bal += imp * load;
        ue  -= load * logf(load + 1e-8f);
        out_tail[3 + e]  = load;
        out_tail[11 + e] = imp;
    }
    out_tail[0] = (float)Eq * bal;
    out_tail[1] = g_ent_sum * invN;
    out_tail[2] = ue;
}

// -------------------- scatter: compact per-expert row lists ---------------
__global__ void scatter_k() {
    int t = blockIdx.x * blockDim.x + threadIdx.x;
    if (t >= Nq) return;
    #pragma unroll
    for (int k = 0; k < Kq; k++) {
        int e = g_tk_idx[2*t + k];
        int pos = atomicAdd(&g_cursor[e], 1);
        g_row_token[pos] = t;
        g_row_gate[pos]  = g_tk_gate[2*t + k];
    }
}

// -------------------- z = x (residual init) -------------------------------
__global__ void zinit_k(const float* __restrict__ x) {
    size_t i = (size_t)blockIdx.x * blockDim.x + threadIdx.x;
    reinterpret_cast<float4*>(g_z)[i] = reinterpret_cast<const float4*>(x)[i];
}

// ==========================================================================
// tf32 tensor-core grouped GEMMs, cp.async double-buffered.
// Tile 128x128x32, 256 threads = 8 warps (2m x 4n), warp tile 64x32.
// A smem [128][36] row-major (conflict-free frag loads, cp.async-friendly
// gather of 16B chunks along k). B smem [32][136].
// Raw fp32 bits fed to mma.tf32 (hw truncation) -> no cvt in load path.
// ==========================================================================

// -------------------- GEMM1: h = gelu(Xg @ W1[e] + b1[e]) -----------------
__global__ __launch_bounds__(256) void gemm1_k(const float* __restrict__ x,
                                               const float* __restrict__ W1,
                                               const float* __restrict__ b1) {
    int e  = blockIdx.x >> 6;
    int mt = blockIdx.x & 63;
    int rows = g_count[e];
    int m0 = mt * 128;
    if (m0 >= rows) return;
    int base = g_offset[e];
    int n0 = blockIdx.y * 128;

    extern __shared__ float sm[];
    int tid = threadIdx.x;

    // ---- prefetch indexing ----
    int arow = tid >> 1;                 // A: 2 threads per row, 4 chunks each
    int akb  = (tid & 1) * 16;           // k offset (floats) of this thread's chunks
    bool av  = (m0 + arow) < rows;
    int atok = av ? g_row_token[base + m0 + arow] : 0;
    const float* agp = x + (size_t)atok * Dq + akb;
    int asz = av ? 16 : 0;

    int bkr = tid >> 3;                  // B: 8 threads per k-row, 4 chunks each
    int bnb = (tid & 7) * 16;
    const float* w1e = W1 + (size_t)e * Dq * Hq;
    const float* bgp = w1e + (size_t)bkr * Hq + n0 + bnb;

    uint32_t a_sm = (uint32_t)__cvta_generic_to_shared(sm + arow * AS_STRIDE + akb);
    uint32_t b_sm = (uint32_t)__cvta_generic_to_shared(sm + A_STAGE_F + bkr * BS_STRIDE + bnb);

    // ---- compute indexing ----
    int warp = tid >> 5, lane = tid & 31;
    int wm = (warp >> 2) * 64, wn = (warp & 3) * 32;
    int qr = lane >> 2, qc = lane & 3;

    float acc[4][4][4];
    #pragma unroll
    for (int mi = 0; mi < 4; mi++)
        #pragma unroll
        for (int ni = 0; ni < 4; ni++)
            #pragma unroll
            for (int j = 0; j < 4; j++) acc[mi][ni][j] = 0.f;

    // prefetch stage 0
    #pragma unroll
    for (int c = 0; c < 4; c++) {
        cp16(a_sm + c * 16, agp + c * 4, asz);
        cp16(b_sm + c * 16, bgp + c * 4, 16);
    }
    CP_COMMIT();

    const int NKT = Dq / KT;
    for (int kt = 0; kt < NKT; kt++) {
        CP_WAIT0();
        __syncthreads();
        int cur = kt & 1;
        if (kt + 1 < NKT) {
            int nxt = cur ^ 1;
            uint32_t ao = a_sm + nxt * (STAGE_F * 4);
            uint32_t bo = b_sm + nxt * (STAGE_F * 4);
            const float* ag = agp + (kt + 1) * KT;
            const float* bg = bgp + (size_t)(kt + 1) * KT * Hq;
            #pragma unroll
            for (int c = 0; c < 4; c++) {
                cp16(ao + c * 16, ag + c * 4, asz);
                cp16(bo + c * 16, bg + c * 4, 16);
            }
            CP_COMMIT();
        }
        const float* As = sm + cur * STAGE_F;
        const float* Bs = As + A_STAGE_F;
        #pragma unroll
        for (int ks = 0; ks < KT; ks += 8) {
            uint32_t af[4][4], bf[4][2];
            #pragma unroll
            for (int mi = 0; mi < 4; mi++) {
                int mb = wm + mi * 16 + qr;
                af[mi][0] = __float_as_uint(As[mb * AS_STRIDE + ks + qc]);
                af[mi][1] = __float_as_uint(As[(mb + 8) * AS_STRIDE + ks + qc]);
                af[mi][2] = __float_as_uint(As[mb * AS_STRIDE + ks + qc + 4]);
                af[mi][3] = __float_as_uint(As[(mb + 8) * AS_STRIDE + ks + qc + 4]);
            }
            #pragma unroll
            for (int ni = 0; ni < 4; ni++) {
                int nb = wn + ni * 8 + qr;
                bf[ni][0] = __float_as_uint(Bs[(ks + qc) * BS_STRIDE + nb]);
                bf[ni][1] = __float_as_uint(Bs[(ks + qc + 4) * BS_STRIDE + nb]);
            }
            #pragma unroll
            for (int mi = 0; mi < 4; mi++)
                #pragma unroll
                for (int ni = 0; ni < 4; ni++)
                    mma8(acc[mi][ni], af[mi][0], af[mi][1], af[mi][2], af[mi][3],
                         bf[ni][0], bf[ni][1]);
        }
        __syncthreads();
    }

    // epilogue: bias + exact gelu -> g_h
    #pragma unroll
    for (int mi = 0; mi < 4; mi++) {
        #pragma unroll
        for (int h = 0; h < 2; h++) {
            int r = wm + mi * 16 + qr + h * 8;
            if (m0 + r < rows) {
                size_t gr = (size_t)(base + m0 + r);
                float* hrow = g_h + gr * Hq;
                #pragma unroll
                for (int ni = 0; ni < 4; ni++) {
                    int c = n0 + wn + ni * 8 + qc * 2;
                    float u = acc[mi][ni][h*2+0] + b1[e * Hq + c];
                    float v = acc[mi][ni][h*2+1] + b1[e * Hq + c + 1];
                    hrow[c]     = gelu_exact(u);
                    hrow[c + 1] = gelu_exact(v);
                }
            }
        }
    }
}

// -------------------- GEMM2: z += gate * (H @ W2[e] + b2[e]) --------------
__global__ __launch_bounds__(256) void gemm2_k(const float* __restrict__ W2,
                                               const float* __restrict__ b2) {
    int e  = blockIdx.x >> 6;
    int mt = blockIdx.x & 63;
    int rows = g_count[e];
    int m0 = mt * 128;
    if (m0 >= rows) return;
    int base = g_offset[e];
    int n0 = blockIdx.y * 128;

    extern __shared__ float sm[];
    int tid = threadIdx.x;

    int arow = tid >> 1;
    int akb  = (tid & 1) * 16;
    bool av  = (m0 + arow) < rows;
    const float* agp = g_h + (size_t)(base + m0 + (av ? arow : 0)) * Hq + akb;
    int asz = av ? 16 : 0;

    int bkr = tid >> 3;
    int bnb = (tid & 7) * 16;
    const float* w2e = W2 + (size_t)e * Hq * Dq;
    const float* bgp = w2e + (size_t)bkr * Dq + n0 + bnb;

    uint32_t a_sm = (uint32_t)__cvta_generic_to_shared(sm + arow * AS_STRIDE + akb);
    uint32_t b_sm = (uint32_t)__cvta_generic_to_shared(sm + A_STAGE_F + bkr * BS_STRIDE + bnb);

    int warp = tid >> 5, lane = tid & 31;
    int wm = (warp >> 2) * 64, wn = (warp & 3) * 32;
    int qr = lane >> 2, qc = lane & 3;

    float acc[4][4][4];
    #pragma unroll
    for (int mi = 0; mi < 4; mi++)
        #pragma unroll
        for (int ni = 0; ni < 4; ni++)
            #pragma unroll
            for (int j = 0; j < 4; j++) acc[mi][ni][j] = 0.f;

    #pragma unroll
    for (int c = 0; c < 4; c++) {
        cp16(a_sm + c * 16, agp + c * 4, asz);
        cp16(b_sm + c * 16, bgp + c * 4, 16);
    }
    CP_COMMIT();

    const int NKT = Hq / KT;
    for (int kt = 0; kt < NKT; kt++) {
        CP_WAIT0();
        __syncthreads();
        int cur = kt & 1;
        if (kt + 1 < NKT) {
            int nxt = cur ^ 1;
            uint32_t ao = a_sm + nxt * (STAGE_F * 4);
            uint32_t bo = b_sm + nxt * (STAGE_F * 4);
            const float* ag = agp + (kt + 1) * KT;
            const float* bg = bgp + (size_t)(kt + 1) * KT * Dq;
            #pragma unroll
            for (int c = 0; c < 4; c++) {
                cp16(ao + c * 16, ag + c * 4, asz);
                cp16(bo + c * 16, bg + c * 4, 16);
            }
            CP_COMMIT();
        }
        const float* As = sm + cur * STAGE_F;
        const float* Bs = As + A_STAGE_F;
        #pragma unroll
        for (int ks = 0; ks < KT; ks += 8) {
            uint32_t af[4][4], bf[4][2];
            #pragma unroll
            for (int mi = 0; mi < 4; mi++) {
                int mb = wm + mi * 16 + qr;
                af[mi][0] = __float_as_uint(As[mb * AS_STRIDE + ks + qc]);
                af[mi][1] = __float_as_uint(As[(mb + 8) * AS_STRIDE + ks + qc]);
                af[mi][2] = __float_as_uint(As[mb * AS_STRIDE + ks + qc + 4]);
                af[mi][3] = __float_as_uint(As[(mb + 8) * AS_STRIDE + ks + qc + 4]);
            }
            #pragma unroll
            for (int ni = 0; ni < 4; ni++) {
                int nb = wn + ni * 8 + qr;
                bf[ni][0] = __float_as_uint(Bs[(ks + qc) * BS_STRIDE + nb]);
                bf[ni][1] = __float_as_uint(Bs[(ks + qc + 4) * BS_STRIDE + nb]);
            }
            #pragma unroll
            for (int mi = 0; mi < 4; mi++)
                #pragma unroll
                for (int ni = 0; ni < 4; ni++)
                    mma8(acc[mi][ni], af[mi][0], af[mi][1], af[mi][2], af[mi][3],
                         bf[ni][0], bf[ni][1]);
        }
        __syncthreads();
    }

    // epilogue: gate * (acc + b2) scattered into residual accumulator
    #pragma unroll
    for (int mi = 0; mi < 4; mi++) {
        #pragma unroll
        for (int h = 0; h < 2; h++) {
            int r = wm + mi * 16 + qr + h * 8;
            if (m0 + r < rows) {
                int gr = base + m0 + r;
                int tok  = g_row_token[gr];
                float gt = g_row_gate[gr];
                float* zr = g_z + (size_t)tok * Dq;
                #pragma unroll
                for (int ni = 0; ni < 4; ni++) {
                    int c = n0 + wn + ni * 8 + qc * 2;
                    atomicAdd(&zr[c],     gt * (acc[mi][ni][h*2+0] + b2[e * Dq + c]));
                    atomicAdd(&zr[c + 1], gt * (acc[mi][ni][h*2+1] + b2[e * Dq + c + 1]));
                }
            }
        }
    }
}

// -------------------- layernorm: one block (256 thr) per token ------------
__global__ void ln_k(const float* __restrict__ gamma,
                     const float* __restrict__ beta,
                     float* __restrict__ out) {
    int t = blockIdx.x;
    int tid = threadIdx.x;
    const float4* zr = reinterpret_cast<const float4*>(g_z + (size_t)t * Dq);
    float4 v = zr[tid];
    float s  = v.x + v.y + v.z + v.w;
    float ss = v.x*v.x + v.y*v.y + v.z*v.z + v.w*v.w;

    #pragma unroll
    for (int o = 16; o > 0; o >>= 1) {
        s  += __shfl_down_sync(0xffffffffu, s, o);
        ss += __shfl_down_sync(0xffffffffu, ss, o);
    }
    __shared__ float rs[8], rss[8];
    int warp = tid >> 5, lane = tid & 31;
    if (lane == 0) { rs[warp] = s; rss[warp] = ss; }
    __syncthreads();
    if (warp == 0) {
        float a = (lane < 8) ? rs[lane] : 0.f;
        float b = (lane < 8) ? rss[lane] : 0.f;
        #pragma unroll
        for (int o = 4; o > 0; o >>= 1) {
            a += __shfl_down_sync(0xffffffffu, a, o);
            b += __shfl_down_sync(0xffffffffu, b, o);
        }
        if (lane == 0) { rs[0] = a; rss[0] = b; }
    }
    __syncthreads();
    float mu  = rs[0] * (1.f / Dq);
    float var = rss[0] * (1.f / Dq) - mu * mu;
    float rstd = rsqrtf(var + 1e-5f);

    float4 g = reinterpret_cast<const float4*>(gamma)[tid];
    float4 bta = reinterpret_cast<const float4*>(beta)[tid];
    float4 o4;
    o4.x = (v.x - mu) * rstd * g.x + bta.x;
    o4.y = (v.y - mu) * rstd * g.y + bta.y;
    o4.z = (v.z - mu) * rstd * g.z + bta.z;
    o4.w = (v.w - mu) * rstd * g.w + bta.w;
    reinterpret_cast<float4*>(out + (size_t)t * Dq)[tid] = o4;
}

// -------------------- launch ----------------------------------------------
extern "C" void kernel_launch(void* const* d_in, const int* in_sizes, int n_in,
                              void* d_out, int out_size) {
    const float* x     = (const float*)d_in[0];
    const float* gw    = (const float*)d_in[1];
    const float* gb    = (const float*)d_in[2];
    const float* W1    = (const float*)d_in[3];
    const float* b1    = (const float*)d_in[4];
    const float* W2    = (const float*)d_in[5];
    const float* b2    = (const float*)d_in[6];
    const float* gamma = (const float*)d_in[7];
    const float* beta  = (const float*)d_in[8];
    float* out = (float*)d_out;

    static bool attr_set = false;
    if (!attr_set) {
        cudaFuncSetAttribute(gemm1_k, cudaFuncAttributeMaxDynamicSharedMemorySize, SMEM_BYTES);
        cudaFuncSetAttribute(gemm2_k, cudaFuncAttributeMaxDynamicSharedMemorySize, SMEM_BYTES);
        attr_set = true;
    }

    init_k<<<1, 32>>>();
    router_k<<<Nq / 8, 256>>>(x, gw, gb);
    finalize_k<<<1, 32>>>(out + (size_t)Nq * Dq);
    scatter_k<<<Nq / 256, 256>>>();
    zinit_k<<<(Nq * Dq / 4) / 256, 256>>>(x);
    gemm1_k<<<dim3(Eq * MTILES, Hq / 128), 256, SMEM_BYTES>>>(x, W1, b1);
    gemm2_k<<<dim3(Eq * MTILES, Dq / 128), 256, SMEM_BYTES>>>(W2, b2);
    ln_k<<<Nq, 256>>>(gamma, beta, out);
    (void)in_sizes; (void)n_in; (void)out_size;
}